// round 1
// baseline (speedup 1.0000x reference)
#include <cuda_runtime.h>
#include <cuda_bf16.h>

// Problem constants
#define B_    4
#define S_    2048
#define NX_   1024
#define NH_   16
#define HD_   64
#define N3X_  (3 * NX_)     // 3072
#define MROWS (B_ * S_)     // 8192

// Scratch (allocation-free rule: __device__ globals)
__device__ float g_qkv[MROWS * N3X_];   // [8192, 3072]  (~96 MB)
__device__ float g_attn[MROWS * NX_];   // [8192, 1024]  (~32 MB)

// ---------------------------------------------------------------------------
// SGEMM: C[M,N] = A[M,K] @ W[K,N] + bias[N]
// BM=128, BN=128, BK=8, 256 threads, 8x8 per-thread microtile
// ---------------------------------------------------------------------------
#define BM 128
#define BN 128
#define BKK 8
#define TM 8
#define TN 8

__global__ __launch_bounds__(256)
void sgemm_bias_kernel(const float* __restrict__ A,
                       const float* __restrict__ W,
                       const float* __restrict__ bias,
                       float* __restrict__ C,
                       int M, int N, int K)
{
    __shared__ float As[BKK][BM];
    __shared__ float Bs[BKK][BN];

    const int tid = threadIdx.x;              // 0..255
    const int tr  = tid / (BN / TN);          // 0..15
    const int tc  = tid % (BN / TN);          // 0..15
    const int rowBase = blockIdx.y * BM;
    const int colBase = blockIdx.x * BN;

    // A tile load mapping: one float4 per thread along K
    const int aRow = tid >> 1;                // 0..127
    const int aCol = (tid & 1) * 4;           // 0 or 4
    // B tile load mapping: one float4 per thread along N
    const int bRow = tid >> 5;                // 0..7
    const int bCol = (tid & 31) * 4;          // 0..124

    float acc[TM][TN];
#pragma unroll
    for (int i = 0; i < TM; i++)
#pragma unroll
        for (int j = 0; j < TN; j++) acc[i][j] = 0.0f;

    const float* Aptr = A + (long)rowBase * K;
    const float* Wptr = W + colBase;

    for (int k0 = 0; k0 < K; k0 += BKK) {
        float4 av = *(const float4*)(Aptr + (long)aRow * K + k0 + aCol);
        As[aCol + 0][aRow] = av.x;
        As[aCol + 1][aRow] = av.y;
        As[aCol + 2][aRow] = av.z;
        As[aCol + 3][aRow] = av.w;
        float4 bv = *(const float4*)(Wptr + (long)(k0 + bRow) * N + bCol);
        *(float4*)&Bs[bRow][bCol] = bv;
        __syncthreads();

#pragma unroll
        for (int k = 0; k < BKK; k++) {
            float regM[TM], regN[TN];
#pragma unroll
            for (int i = 0; i < TM; i++) regM[i] = As[k][tr * TM + i];
#pragma unroll
            for (int j = 0; j < TN; j++) regN[j] = Bs[k][tc * TN + j];
#pragma unroll
            for (int i = 0; i < TM; i++)
#pragma unroll
                for (int j = 0; j < TN; j++)
                    acc[i][j] = fmaf(regM[i], regN[j], acc[i][j]);
        }
        __syncthreads();
    }

#pragma unroll
    for (int i = 0; i < TM; i++) {
        const int r = rowBase + tr * TM + i;
#pragma unroll
        for (int j = 0; j < TN; j += 4) {
            const int c = colBase + tc * TN + j;
            float4 o;
            o.x = acc[i][j + 0] + bias[c + 0];
            o.y = acc[i][j + 1] + bias[c + 1];
            o.z = acc[i][j + 2] + bias[c + 2];
            o.w = acc[i][j + 3] + bias[c + 3];
            *(float4*)(C + (long)r * N + c) = o;
        }
    }
}

// ---------------------------------------------------------------------------
// Flash attention over g_qkv -> g_attn.
// Per block: (q_tile 64, head, batch). K tiles of 64, causal skip.
// Online softmax; everything fp32.
// blockDim = (16,16). Thread (tx,ty) owns q-rows {ty+16i} x cols {tx+16j}.
// ---------------------------------------------------------------------------
#define BQ  64
#define BKT 64
#define SD  68   // smem row stride (floats), padded: conflict-free & 16B-aligned

__global__ __launch_bounds__(256)
void attention_kernel(const float* __restrict__ qkv,
                      float* __restrict__ outa)
{
    extern __shared__ float sm[];
    float* Qs   = sm;                    // 64*68
    float* Ks   = Qs + BQ * SD;          // 64*68
    float* Vs   = Ks + BKT * SD;         // 64*68
    float* Ps   = Vs + BKT * SD;         // 64*68 (scores then probs)
    float* mrow = Ps + BQ * SD;          // 64
    float* lrow = mrow + BQ;             // 64
    float* crow = lrow + BQ;             // 64

    const int tx  = threadIdx.x;         // 0..15
    const int ty  = threadIdx.y;         // 0..15
    const int tid = ty * 16 + tx;
    const int qt  = blockIdx.x;          // 0..31
    const int h   = blockIdx.y;          // 0..15
    const int b   = blockIdx.z;          // 0..3
    const int q0  = qt * BQ;
    const int qoff = h * HD_;
    const float scale = 0.125f;          // 1/sqrt(64)

    // Load Q tile (pre-scaled)
    for (int idx = tid; idx < BQ * 16; idx += 256) {
        int r = idx >> 4;
        int d = (idx & 15) * 4;
        float4 v = *(const float4*)(qkv + (long)(b * S_ + q0 + r) * N3X_ + qoff + d);
        v.x *= scale; v.y *= scale; v.z *= scale; v.w *= scale;
        *(float4*)&Qs[r * SD + d] = v;
    }
    if (tid < BQ) { mrow[tid] = -1e30f; lrow[tid] = 0.0f; }

    float o[4][4];
#pragma unroll
    for (int i = 0; i < 4; i++)
#pragma unroll
        for (int j = 0; j < 4; j++) o[i][j] = 0.0f;

    for (int kt = 0; kt <= qt; kt++) {
        const int k0 = kt * BKT;
        __syncthreads();   // prior-iter consumers done (and Q/m/l init on iter 0)

        // Load K and V tiles
        for (int idx = tid; idx < BKT * 16; idx += 256) {
            int r = idx >> 4;
            int d = (idx & 15) * 4;
            long grow = (long)(b * S_ + k0 + r) * N3X_ + qoff;
            *(float4*)&Ks[r * SD + d] = *(const float4*)(qkv + grow + NX_  + d);
            *(float4*)&Vs[r * SD + d] = *(const float4*)(qkv + grow + 2 * NX_ + d);
        }
        __syncthreads();

        // --- Scores: S = (Q*scale) @ K^T ---
        float acc[4][4];
#pragma unroll
        for (int i = 0; i < 4; i++)
#pragma unroll
            for (int j = 0; j < 4; j++) acc[i][j] = 0.0f;

        for (int d = 0; d < HD_; d += 4) {
            float4 q4[4], k4[4];
#pragma unroll
            for (int i = 0; i < 4; i++)
                q4[i] = *(const float4*)&Qs[(ty + 16 * i) * SD + d];
#pragma unroll
            for (int j = 0; j < 4; j++)
                k4[j] = *(const float4*)&Ks[(tx + 16 * j) * SD + d];
#pragma unroll
            for (int i = 0; i < 4; i++)
#pragma unroll
                for (int j = 0; j < 4; j++) {
                    acc[i][j] = fmaf(q4[i].x, k4[j].x, acc[i][j]);
                    acc[i][j] = fmaf(q4[i].y, k4[j].y, acc[i][j]);
                    acc[i][j] = fmaf(q4[i].z, k4[j].z, acc[i][j]);
                    acc[i][j] = fmaf(q4[i].w, k4[j].w, acc[i][j]);
                }
        }

        const bool diag = (kt == qt);
#pragma unroll
        for (int i = 0; i < 4; i++) {
            const int qi = q0 + ty + 16 * i;
#pragma unroll
            for (int j = 0; j < 4; j++) {
                const int ki = k0 + tx + 16 * j;
                float s = acc[i][j];
                if (diag && ki > qi) s = -1e30f;   // masked -> exp underflows to 0
                Ps[(ty + 16 * i) * SD + (tx + 16 * j)] = s;
            }
        }
        __syncthreads();

        // --- Online softmax: one warp handles 8 rows ---
        {
            const int w    = tid >> 5;
            const int lane = tid & 31;
#pragma unroll
            for (int rr = 0; rr < 8; rr++) {
                const int r = w * 8 + rr;
                float x0 = Ps[r * SD + lane];
                float x1 = Ps[r * SD + 32 + lane];
                float mx = fmaxf(x0, x1);
#pragma unroll
                for (int off = 16; off > 0; off >>= 1)
                    mx = fmaxf(mx, __shfl_xor_sync(0xffffffffu, mx, off));
                const float mold = mrow[r];
                const float mnew = fmaxf(mold, mx);
                float p0 = __expf(x0 - mnew);
                float p1 = __expf(x1 - mnew);
                float sum = p0 + p1;
#pragma unroll
                for (int off = 16; off > 0; off >>= 1)
                    sum += __shfl_xor_sync(0xffffffffu, sum, off);
                Ps[r * SD + lane]      = p0;
                Ps[r * SD + 32 + lane] = p1;
                if (lane == 0) {
                    const float c = __expf(mold - mnew);
                    lrow[r] = lrow[r] * c + sum;
                    mrow[r] = mnew;
                    crow[r] = c;
                }
            }
        }
        __syncthreads();

        // --- O = O*corr + P @ V ---
        float cr[4];
#pragma unroll
        for (int i = 0; i < 4; i++) cr[i] = crow[ty + 16 * i];
#pragma unroll
        for (int i = 0; i < 4; i++)
#pragma unroll
            for (int j = 0; j < 4; j++) o[i][j] *= cr[i];

        for (int k = 0; k < BKT; k += 4) {
            float4 p4[4];
#pragma unroll
            for (int i = 0; i < 4; i++)
                p4[i] = *(const float4*)&Ps[(ty + 16 * i) * SD + k];
            float vv[4][4];
#pragma unroll
            for (int kk = 0; kk < 4; kk++)
#pragma unroll
                for (int j = 0; j < 4; j++)
                    vv[kk][j] = Vs[(k + kk) * SD + tx + 16 * j];
#pragma unroll
            for (int i = 0; i < 4; i++)
#pragma unroll
                for (int j = 0; j < 4; j++) {
                    o[i][j] = fmaf(p4[i].x, vv[0][j], o[i][j]);
                    o[i][j] = fmaf(p4[i].y, vv[1][j], o[i][j]);
                    o[i][j] = fmaf(p4[i].z, vv[2][j], o[i][j]);
                    o[i][j] = fmaf(p4[i].w, vv[3][j], o[i][j]);
                }
        }
    }

    // Finalize: divide by row sum, write merged-head layout [b, s, h*HD + d]
#pragma unroll
    for (int i = 0; i < 4; i++) {
        const int qr = ty + 16 * i;
        const float inv = 1.0f / lrow[qr];
#pragma unroll
        for (int j = 0; j < 4; j++) {
            const int dc = tx + 16 * j;
            outa[(long)(b * S_ + q0 + qr) * NX_ + h * HD_ + dc] = o[i][j] * inv;
        }
    }
}

// ---------------------------------------------------------------------------
// Launch
// ---------------------------------------------------------------------------
extern "C" void kernel_launch(void* const* d_in, const int* in_sizes, int n_in,
                              void* d_out, int out_size)
{
    (void)in_sizes; (void)n_in; (void)out_size;
    const float* hidden   = (const float*)d_in[0];  // [4,2048,1024]
    const float* c_attn_w = (const float*)d_in[1];  // [1024,3072]
    const float* c_attn_b = (const float*)d_in[2];  // [3072]
    const float* c_proj_w = (const float*)d_in[3];  // [1024,1024]
    const float* c_proj_b = (const float*)d_in[4];  // [1024]
    float* out = (float*)d_out;                     // [4,2048,1024]

    void* qkv_ptr  = nullptr;
    void* attn_ptr = nullptr;
    cudaGetSymbolAddress(&qkv_ptr,  g_qkv);
    cudaGetSymbolAddress(&attn_ptr, g_attn);
    float* qkv  = (float*)qkv_ptr;
    float* attn = (float*)attn_ptr;

    // 1) QKV projection: [8192,1024] @ [1024,3072] + b
    {
        dim3 grid(N3X_ / BN, MROWS / BM);
        sgemm_bias_kernel<<<grid, 256>>>(hidden, c_attn_w, c_attn_b, qkv,
                                         MROWS, N3X_, NX_);
    }

    // 2) Causal flash attention
    {
        const int smem = (4 * BQ * SD + 3 * BQ) * (int)sizeof(float); // 70400 B
        cudaFuncSetAttribute(attention_kernel,
                             cudaFuncAttributeMaxDynamicSharedMemorySize, smem);
        dim3 grid(S_ / BQ, NH_, B_);
        dim3 block(16, 16);
        attention_kernel<<<grid, block, smem>>>(qkv, attn);
    }

    // 3) Output projection: [8192,1024] @ [1024,1024] + b
    {
        dim3 grid(NX_ / BN, MROWS / BM);
        sgemm_bias_kernel<<<grid, 256>>>(attn, c_proj_w, c_proj_b, out,
                                         MROWS, NX_, NX_);
    }
}

// round 3
// speedup vs baseline: 1.6083x; 1.6083x over previous
#include <cuda_runtime.h>
#include <cuda_bf16.h>
#include <cstdint>

// Problem constants
#define B_    4
#define S_    2048
#define NX_   1024
#define NH_   16
#define HD_   64
#define N3X_  (3 * NX_)     // 3072
#define MROWS (B_ * S_)     // 8192

// ---------------------------------------------------------------------------
// Scratch (__device__ globals: allocation-free rule)
// ---------------------------------------------------------------------------
__device__ float g_qkv[MROWS * N3X_];            // [8192, 3072] fp32
__device__ float g_attn[MROWS * NX_];            // [8192, 1024] fp32
__device__ __nv_bfloat16 g_xhi[MROWS * NX_];     // activation split hi
__device__ __nv_bfloat16 g_xlo[MROWS * NX_];     // activation split lo
__device__ __nv_bfloat16 g_wqT_hi[N3X_ * NX_];   // c_attn_w^T  [3072,1024]
__device__ __nv_bfloat16 g_wqT_lo[N3X_ * NX_];
__device__ __nv_bfloat16 g_wpT_hi[NX_ * NX_];    // c_proj_w^T  [1024,1024]
__device__ __nv_bfloat16 g_wpT_lo[NX_ * NX_];

// ---------------------------------------------------------------------------
// PTX helpers — ONLY non-arch-specific instructions (plain sm_103 target):
// mma.sync (sm_80), ldmatrix (sm_75), cp.async (sm_80).
// ---------------------------------------------------------------------------
__device__ __forceinline__ uint32_t smem_to_u32(const void* p) {
    uint32_t a;
    asm("{ .reg .u64 t; cvta.to.shared.u64 t, %1; cvt.u32.u64 %0, t; }"
        : "=r"(a) : "l"(p));
    return a;
}

#define SWZ128(b) ((b) ^ (((b) >> 3) & 0x70))

#define CP_ASYNC16(saddr, gptr) \
    asm volatile("cp.async.cg.shared.global [%0], [%1], 16;" \
        :: "r"(saddr), "l"(gptr) : "memory")
#define CP_COMMIT()  asm volatile("cp.async.commit_group;" ::: "memory")
#define CP_WAIT1()   asm volatile("cp.async.wait_group 1;" ::: "memory")

#define LDSM_X4(r0, r1, r2, r3, addr) \
    asm volatile("ldmatrix.sync.aligned.m8n8.x4.shared.b16 {%0,%1,%2,%3}, [%4];" \
        : "=r"(r0), "=r"(r1), "=r"(r2), "=r"(r3) : "r"(addr))

#define MMA_BF16(c, a, b0v, b1v) \
    asm volatile("mma.sync.aligned.m16n8k16.row.col.f32.bf16.bf16.f32 " \
        "{%0,%1,%2,%3}, {%4,%5,%6,%7}, {%8,%9}, {%0,%1,%2,%3};" \
        : "+f"((c)[0]), "+f"((c)[1]), "+f"((c)[2]), "+f"((c)[3]) \
        : "r"((a)[0]), "r"((a)[1]), "r"((a)[2]), "r"((a)[3]), \
          "r"(b0v), "r"(b1v))

// ---------------------------------------------------------------------------
// Conversion kernels
// ---------------------------------------------------------------------------
__global__ void split_bf16_kernel(const float* __restrict__ x,
                                  __nv_bfloat16* __restrict__ hi,
                                  __nv_bfloat16* __restrict__ lo, int n4)
{
    int i = blockIdx.x * blockDim.x + threadIdx.x;
    if (i >= n4) return;
    float4 v = ((const float4*)x)[i];
    __nv_bfloat16 h0 = __float2bfloat16(v.x);
    __nv_bfloat16 h1 = __float2bfloat16(v.y);
    __nv_bfloat16 h2 = __float2bfloat16(v.z);
    __nv_bfloat16 h3 = __float2bfloat16(v.w);
    __nv_bfloat16 l0 = __float2bfloat16(v.x - __bfloat162float(h0));
    __nv_bfloat16 l1 = __float2bfloat16(v.y - __bfloat162float(h1));
    __nv_bfloat16 l2 = __float2bfloat16(v.z - __bfloat162float(h2));
    __nv_bfloat16 l3 = __float2bfloat16(v.w - __bfloat162float(h3));
    __nv_bfloat162* hp = (__nv_bfloat162*)hi;
    __nv_bfloat162* lp = (__nv_bfloat162*)lo;
    hp[2 * i]     = __nv_bfloat162(h0, h1);
    hp[2 * i + 1] = __nv_bfloat162(h2, h3);
    lp[2 * i]     = __nv_bfloat162(l0, l1);
    lp[2 * i + 1] = __nv_bfloat162(l2, l3);
}

// W [K,N] fp32 -> W^T [N,K] bf16 hi/lo
__global__ void transpose_split_kernel(const float* __restrict__ W,
                                       __nv_bfloat16* __restrict__ hiT,
                                       __nv_bfloat16* __restrict__ loT,
                                       int K, int N)
{
    __shared__ float t[32][33];
    const int nB = blockIdx.x * 32;
    const int kB = blockIdx.y * 32;
    const int tx = threadIdx.x, ty = threadIdx.y;   // 32x8
#pragma unroll
    for (int i = 0; i < 4; i++)
        t[ty + 8 * i][tx] = W[(long)(kB + ty + 8 * i) * N + nB + tx];
    __syncthreads();
#pragma unroll
    for (int i = 0; i < 4; i++) {
        float v = t[tx][ty + 8 * i];
        __nv_bfloat16 h = __float2bfloat16(v);
        long o = (long)(nB + ty + 8 * i) * K + kB + tx;
        hiT[o] = h;
        loT[o] = __float2bfloat16(v - __bfloat162float(h));
    }
}

// ---------------------------------------------------------------------------
// bf16-split GEMM via mma.sync: C[M,N] = A[M,K] @ W[K,N] + bias
// A: hi/lo [M,K] bf16.  W passed transposed: [N,K] bf16 hi/lo.
// CTA tile 128x128. 8 warps -> warp tile 64x32 (wm in {0,1}, wn in {0..3}).
// K-chunks of 64 elements (128B rows, SW128 swizzle), cp.async double buffer.
// D = Ahi*Bhi + Ahi*Blo + Alo*Bhi  (fp32 accum).
// ---------------------------------------------------------------------------
#define G_TILE_B 16384           // 128 rows * 128 bytes
#define G_BUF_B  (4 * G_TILE_B)  // Ahi, Alo, Bhi, Blo
#define G_SMEM_REQ (2 * G_BUF_B) // 131072

__global__ __launch_bounds__(256, 1)
void gemm_bf16split_mma(const __nv_bfloat16* __restrict__ Ahi,
                        const __nv_bfloat16* __restrict__ Alo,
                        const __nv_bfloat16* __restrict__ Bhi,
                        const __nv_bfloat16* __restrict__ Blo,
                        const float* __restrict__ bias,
                        float* __restrict__ C,
                        int N, int K)
{
    extern __shared__ char smem[];
    const uint32_t sbase = smem_to_u32(smem);

    const int tid  = threadIdx.x;
    const int wid  = tid >> 5;
    const int lane = tid & 31;
    const int wm   = wid & 1;      // 0..1  (64-row slab)
    const int wn   = wid >> 1;     // 0..3  (32-col slab)
    const int rowBase = blockIdx.y * 128;
    const int colBase = blockIdx.x * 128;

    const int NCH = K >> 6;        // 64-element chunks

    // --- chunk loader: 16 cp.async of 16B per thread -----------------------
    const int ldr = tid >> 3;      // 0..31 (row base, step 32)
    const int ldc = tid & 7;       // 16B column within 128B row

    auto load_chunk = [&](int ch) {
        const uint32_t bb = sbase + (uint32_t)(ch & 1) * G_BUF_B;
        const long k0 = (long)ch * 64 + ldc * 8;
#pragma unroll
        for (int i = 0; i < 4; i++) {
            const int r = ldr + i * 32;
            const uint32_t sw = SWZ128((uint32_t)(r * 128 + ldc * 16));
            const long ao = (long)(rowBase + r) * K + k0;
            const long bo = (long)(colBase + r) * K + k0;
            CP_ASYNC16(bb + sw,                 Ahi + ao);
            CP_ASYNC16(bb + G_TILE_B + sw,      Alo + ao);
            CP_ASYNC16(bb + 2 * G_TILE_B + sw,  Bhi + bo);
            CP_ASYNC16(bb + 3 * G_TILE_B + sw,  Blo + bo);
        }
    };

    float acc[4][4][4];
#pragma unroll
    for (int i = 0; i < 4; i++)
#pragma unroll
        for (int j = 0; j < 4; j++)
#pragma unroll
            for (int v = 0; v < 4; v++) acc[i][j][v] = 0.0f;

    // ldmatrix lane addressing (constant per thread)
    const int a_row  = lane & 15;              // row within 16-row frag
    const int a_colb = (lane >> 4) << 4;       // 0 or 16 bytes (k+8)
    const int b_row  = (lane & 7) + ((lane & 16) ? 8 : 0);
    const int b_colb = (lane & 8) ? 16 : 0;

    load_chunk(0);
    CP_COMMIT();

    for (int ch = 0; ch < NCH; ch++) {
        __syncthreads();                       // buf[(ch+1)&1] readers done
        if (ch + 1 < NCH) load_chunk(ch + 1);
        CP_COMMIT();
        CP_WAIT1();                            // chunk ch resident (this thread)
        __syncthreads();                       // resident for all threads

        const uint32_t bb  = sbase + (uint32_t)(ch & 1) * G_BUF_B;
        const uint32_t aHi = bb;
        const uint32_t aLo = bb + G_TILE_B;
        const uint32_t bHi = bb + 2 * G_TILE_B;
        const uint32_t bLo = bb + 3 * G_TILE_B;

#pragma unroll
        for (int ks = 0; ks < 4; ks++) {
            const int kb = ks * 32;            // 16 elems = 32 bytes

            uint32_t ahi[4][4], alo[4][4];
#pragma unroll
            for (int mi = 0; mi < 4; mi++) {
                const int r = wm * 64 + mi * 16 + a_row;
                const uint32_t off = SWZ128((uint32_t)(r * 128 + kb + a_colb));
                LDSM_X4(ahi[mi][0], ahi[mi][1], ahi[mi][2], ahi[mi][3], aHi + off);
                LDSM_X4(alo[mi][0], alo[mi][1], alo[mi][2], alo[mi][3], aLo + off);
            }

            uint32_t bhi[4][2], blo[4][2];
#pragma unroll
            for (int njp = 0; njp < 2; njp++) {
                const int n = wn * 32 + njp * 16 + b_row;
                const uint32_t off = SWZ128((uint32_t)(n * 128 + kb + b_colb));
                uint32_t r0, r1, r2, r3;
                LDSM_X4(r0, r1, r2, r3, bHi + off);
                bhi[njp * 2][0] = r0;     bhi[njp * 2][1] = r1;
                bhi[njp * 2 + 1][0] = r2; bhi[njp * 2 + 1][1] = r3;
                LDSM_X4(r0, r1, r2, r3, bLo + off);
                blo[njp * 2][0] = r0;     blo[njp * 2][1] = r1;
                blo[njp * 2 + 1][0] = r2; blo[njp * 2 + 1][1] = r3;
            }

#pragma unroll
            for (int mi = 0; mi < 4; mi++)
#pragma unroll
                for (int nj = 0; nj < 4; nj++) {
                    MMA_BF16(acc[mi][nj], ahi[mi], bhi[nj][0], bhi[nj][1]);
                    MMA_BF16(acc[mi][nj], ahi[mi], blo[nj][0], blo[nj][1]);
                    MMA_BF16(acc[mi][nj], alo[mi], bhi[nj][0], bhi[nj][1]);
                }
        }
    }

    // Epilogue: write fragments + bias
#pragma unroll
    for (int mi = 0; mi < 4; mi++) {
        const int row = rowBase + wm * 64 + mi * 16 + (lane >> 2);
#pragma unroll
        for (int nj = 0; nj < 4; nj++) {
            const int col = colBase + wn * 32 + nj * 8 + (lane & 3) * 2;
            const float bx = bias[col];
            const float by = bias[col + 1];
            float2 v0, v1;
            v0.x = acc[mi][nj][0] + bx;
            v0.y = acc[mi][nj][1] + by;
            v1.x = acc[mi][nj][2] + bx;
            v1.y = acc[mi][nj][3] + by;
            *(float2*)(C + (long)row * N + col)       = v0;
            *(float2*)(C + (long)(row + 8) * N + col) = v1;
        }
    }
}

// ---------------------------------------------------------------------------
// Flash attention over g_qkv -> g_attn (fp32 FFMA, unchanged from round 1)
// ---------------------------------------------------------------------------
#define BQ  64
#define BKT 64
#define SD  68

__global__ __launch_bounds__(256)
void attention_kernel(const float* __restrict__ qkv,
                      float* __restrict__ outa)
{
    extern __shared__ float sm[];
    float* Qs   = sm;
    float* Ks   = Qs + BQ * SD;
    float* Vs   = Ks + BKT * SD;
    float* Ps   = Vs + BKT * SD;
    float* mrow = Ps + BQ * SD;
    float* lrow = mrow + BQ;
    float* crow = lrow + BQ;

    const int tx  = threadIdx.x;
    const int ty  = threadIdx.y;
    const int tid = ty * 16 + tx;
    const int qt  = blockIdx.x;
    const int h   = blockIdx.y;
    const int b   = blockIdx.z;
    const int q0  = qt * BQ;
    const int qoff = h * HD_;
    const float scale = 0.125f;

    for (int idx = tid; idx < BQ * 16; idx += 256) {
        int r = idx >> 4;
        int d = (idx & 15) * 4;
        float4 v = *(const float4*)(qkv + (long)(b * S_ + q0 + r) * N3X_ + qoff + d);
        v.x *= scale; v.y *= scale; v.z *= scale; v.w *= scale;
        *(float4*)&Qs[r * SD + d] = v;
    }
    if (tid < BQ) { mrow[tid] = -1e30f; lrow[tid] = 0.0f; }

    float o[4][4];
#pragma unroll
    for (int i = 0; i < 4; i++)
#pragma unroll
        for (int j = 0; j < 4; j++) o[i][j] = 0.0f;

    for (int kt = 0; kt <= qt; kt++) {
        const int k0 = kt * BKT;
        __syncthreads();

        for (int idx = tid; idx < BKT * 16; idx += 256) {
            int r = idx >> 4;
            int d = (idx & 15) * 4;
            long grow = (long)(b * S_ + k0 + r) * N3X_ + qoff;
            *(float4*)&Ks[r * SD + d] = *(const float4*)(qkv + grow + NX_  + d);
            *(float4*)&Vs[r * SD + d] = *(const float4*)(qkv + grow + 2 * NX_ + d);
        }
        __syncthreads();

        float acc[4][4];
#pragma unroll
        for (int i = 0; i < 4; i++)
#pragma unroll
            for (int j = 0; j < 4; j++) acc[i][j] = 0.0f;

        for (int d = 0; d < HD_; d += 4) {
            float4 q4[4], k4[4];
#pragma unroll
            for (int i = 0; i < 4; i++)
                q4[i] = *(const float4*)&Qs[(ty + 16 * i) * SD + d];
#pragma unroll
            for (int j = 0; j < 4; j++)
                k4[j] = *(const float4*)&Ks[(tx + 16 * j) * SD + d];
#pragma unroll
            for (int i = 0; i < 4; i++)
#pragma unroll
                for (int j = 0; j < 4; j++) {
                    acc[i][j] = fmaf(q4[i].x, k4[j].x, acc[i][j]);
                    acc[i][j] = fmaf(q4[i].y, k4[j].y, acc[i][j]);
                    acc[i][j] = fmaf(q4[i].z, k4[j].z, acc[i][j]);
                    acc[i][j] = fmaf(q4[i].w, k4[j].w, acc[i][j]);
                }
        }

        const bool diag = (kt == qt);
#pragma unroll
        for (int i = 0; i < 4; i++) {
            const int qi = q0 + ty + 16 * i;
#pragma unroll
            for (int j = 0; j < 4; j++) {
                const int ki = k0 + tx + 16 * j;
                float s = acc[i][j];
                if (diag && ki > qi) s = -1e30f;
                Ps[(ty + 16 * i) * SD + (tx + 16 * j)] = s;
            }
        }
        __syncthreads();

        {
            const int w    = tid >> 5;
            const int lane = tid & 31;
#pragma unroll
            for (int rr = 0; rr < 8; rr++) {
                const int r = w * 8 + rr;
                float x0 = Ps[r * SD + lane];
                float x1 = Ps[r * SD + 32 + lane];
                float mx = fmaxf(x0, x1);
#pragma unroll
                for (int off = 16; off > 0; off >>= 1)
                    mx = fmaxf(mx, __shfl_xor_sync(0xffffffffu, mx, off));
                const float mold = mrow[r];
                const float mnew = fmaxf(mold, mx);
                float p0 = __expf(x0 - mnew);
                float p1 = __expf(x1 - mnew);
                float sum = p0 + p1;
#pragma unroll
                for (int off = 16; off > 0; off >>= 1)
                    sum += __shfl_xor_sync(0xffffffffu, sum, off);
                Ps[r * SD + lane]      = p0;
                Ps[r * SD + 32 + lane] = p1;
                if (lane == 0) {
                    const float c = __expf(mold - mnew);
                    lrow[r] = lrow[r] * c + sum;
                    mrow[r] = mnew;
                    crow[r] = c;
                }
            }
        }
        __syncthreads();

        float cr[4];
#pragma unroll
        for (int i = 0; i < 4; i++) cr[i] = crow[ty + 16 * i];
#pragma unroll
        for (int i = 0; i < 4; i++)
#pragma unroll
            for (int j = 0; j < 4; j++) o[i][j] *= cr[i];

        for (int k = 0; k < BKT; k += 4) {
            float4 p4[4];
#pragma unroll
            for (int i = 0; i < 4; i++)
                p4[i] = *(const float4*)&Ps[(ty + 16 * i) * SD + k];
            float vv[4][4];
#pragma unroll
            for (int kk = 0; kk < 4; kk++)
#pragma unroll
                for (int j = 0; j < 4; j++)
                    vv[kk][j] = Vs[(k + kk) * SD + tx + 16 * j];
#pragma unroll
            for (int i = 0; i < 4; i++)
#pragma unroll
                for (int j = 0; j < 4; j++) {
                    o[i][j] = fmaf(p4[i].x, vv[0][j], o[i][j]);
                    o[i][j] = fmaf(p4[i].y, vv[1][j], o[i][j]);
                    o[i][j] = fmaf(p4[i].z, vv[2][j], o[i][j]);
                    o[i][j] = fmaf(p4[i].w, vv[3][j], o[i][j]);
                }
        }
    }

#pragma unroll
    for (int i = 0; i < 4; i++) {
        const int qr = ty + 16 * i;
        const float inv = 1.0f / lrow[qr];
#pragma unroll
        for (int j = 0; j < 4; j++) {
            const int dc = tx + 16 * j;
            outa[(long)(b * S_ + q0 + qr) * NX_ + h * HD_ + dc] = o[i][j] * inv;
        }
    }
}

// ---------------------------------------------------------------------------
// Launch
// ---------------------------------------------------------------------------
extern "C" void kernel_launch(void* const* d_in, const int* in_sizes, int n_in,
                              void* d_out, int out_size)
{
    (void)in_sizes; (void)n_in; (void)out_size;
    const float* hidden   = (const float*)d_in[0];
    const float* c_attn_w = (const float*)d_in[1];
    const float* c_attn_b = (const float*)d_in[2];
    const float* c_proj_w = (const float*)d_in[3];
    const float* c_proj_b = (const float*)d_in[4];
    float* out = (float*)d_out;

    void *qkv_p, *attn_p, *xhi_p, *xlo_p, *wqh_p, *wql_p, *wph_p, *wpl_p;
    cudaGetSymbolAddress(&qkv_p,  g_qkv);
    cudaGetSymbolAddress(&attn_p, g_attn);
    cudaGetSymbolAddress(&xhi_p,  g_xhi);
    cudaGetSymbolAddress(&xlo_p,  g_xlo);
    cudaGetSymbolAddress(&wqh_p,  g_wqT_hi);
    cudaGetSymbolAddress(&wql_p,  g_wqT_lo);
    cudaGetSymbolAddress(&wph_p,  g_wpT_hi);
    cudaGetSymbolAddress(&wpl_p,  g_wpT_lo);
    float* qkv  = (float*)qkv_p;
    float* attn = (float*)attn_p;
    __nv_bfloat16* xhi = (__nv_bfloat16*)xhi_p;
    __nv_bfloat16* xlo = (__nv_bfloat16*)xlo_p;
    __nv_bfloat16* wqh = (__nv_bfloat16*)wqh_p;
    __nv_bfloat16* wql = (__nv_bfloat16*)wql_p;
    __nv_bfloat16* wph = (__nv_bfloat16*)wph_p;
    __nv_bfloat16* wpl = (__nv_bfloat16*)wpl_p;

    static bool attr_done = false;
    if (!attr_done) {
        cudaFuncSetAttribute(gemm_bf16split_mma,
                             cudaFuncAttributeMaxDynamicSharedMemorySize, G_SMEM_REQ);
        cudaFuncSetAttribute(attention_kernel,
                             cudaFuncAttributeMaxDynamicSharedMemorySize,
                             (4 * BQ * SD + 3 * BQ) * (int)sizeof(float));
        attr_done = true;
    }

    // 1) split activations to bf16 hi/lo
    {
        int n4 = MROWS * NX_ / 4;
        split_bf16_kernel<<<(n4 + 255) / 256, 256>>>(hidden, xhi, xlo, n4);
    }
    // 2) transpose+split weights
    {
        dim3 g1(N3X_ / 32, NX_ / 32);
        transpose_split_kernel<<<g1, dim3(32, 8)>>>(c_attn_w, wqh, wql, NX_, N3X_);
        dim3 g2(NX_ / 32, NX_ / 32);
        transpose_split_kernel<<<g2, dim3(32, 8)>>>(c_proj_w, wph, wpl, NX_, NX_);
    }
    // 3) QKV projection (tensor cores, bf16x3)
    {
        dim3 grid(N3X_ / 128, MROWS / 128);
        gemm_bf16split_mma<<<grid, 256, G_SMEM_REQ>>>(xhi, xlo, wqh, wql,
                                                      c_attn_b, qkv, N3X_, NX_);
    }
    // 4) causal flash attention (fp32)
    {
        const int smem = (4 * BQ * SD + 3 * BQ) * (int)sizeof(float);
        dim3 grid(S_ / BQ, NH_, B_);
        attention_kernel<<<grid, dim3(16, 16), smem>>>(qkv, attn);
    }
    // 5) split attention output
    {
        int n4 = MROWS * NX_ / 4;
        split_bf16_kernel<<<(n4 + 255) / 256, 256>>>(attn, xhi, xlo, n4);
    }
    // 6) output projection (tensor cores, bf16x3)
    {
        dim3 grid(NX_ / 128, MROWS / 128);
        gemm_bf16split_mma<<<grid, 256, G_SMEM_REQ>>>(xhi, xlo, wph, wpl,
                                                      c_proj_b, out, NX_, NX_);
    }
}

// round 4
// speedup vs baseline: 3.5539x; 2.2097x over previous
#include <cuda_runtime.h>
#include <cuda_bf16.h>
#include <cstdint>

// Problem constants
#define B_    4
#define S_    2048
#define NX_   1024
#define NH_   16
#define HD_   64
#define N3X_  (3 * NX_)     // 3072
#define MROWS (B_ * S_)     // 8192

// ---------------------------------------------------------------------------
// Scratch (__device__ globals)
// ---------------------------------------------------------------------------
__device__ __nv_bfloat16 g_xhi[MROWS * NX_];     // activation split hi
__device__ __nv_bfloat16 g_xlo[MROWS * NX_];
__device__ __nv_bfloat16 g_wqT_hi[N3X_ * NX_];   // c_attn_w^T [3072,1024]
__device__ __nv_bfloat16 g_wqT_lo[N3X_ * NX_];
__device__ __nv_bfloat16 g_wpT_hi[NX_ * NX_];    // c_proj_w^T [1024,1024]
__device__ __nv_bfloat16 g_wpT_lo[NX_ * NX_];
// attention operands, [b,h,s,d] bf16 hi/lo (Q pre-scaled by 0.125)
__device__ __nv_bfloat16 g_qhi[MROWS * NX_];
__device__ __nv_bfloat16 g_qlo[MROWS * NX_];
__device__ __nv_bfloat16 g_khi[MROWS * NX_];
__device__ __nv_bfloat16 g_klo[MROWS * NX_];
__device__ __nv_bfloat16 g_vhi[MROWS * NX_];
__device__ __nv_bfloat16 g_vlo[MROWS * NX_];

// ---------------------------------------------------------------------------
// PTX helpers (non-arch-specific only: sm_80-era mma/ldmatrix/cp.async)
// ---------------------------------------------------------------------------
__device__ __forceinline__ uint32_t smem_to_u32(const void* p) {
    uint32_t a;
    asm("{ .reg .u64 t; cvta.to.shared.u64 t, %1; cvt.u32.u64 %0, t; }"
        : "=r"(a) : "l"(p));
    return a;
}

#define SWZ128(b) ((b) ^ (((b) >> 3) & 0x70))

#define CP_ASYNC16(saddr, gptr) \
    asm volatile("cp.async.cg.shared.global [%0], [%1], 16;" \
        :: "r"(saddr), "l"(gptr) : "memory")
#define CP_COMMIT()  asm volatile("cp.async.commit_group;" ::: "memory")
#define CP_WAIT1()   asm volatile("cp.async.wait_group 1;" ::: "memory")
#define CP_WAIT0()   asm volatile("cp.async.wait_group 0;" ::: "memory")

#define LDSM_X4(r0, r1, r2, r3, addr) \
    asm volatile("ldmatrix.sync.aligned.m8n8.x4.shared.b16 {%0,%1,%2,%3}, [%4];" \
        : "=r"(r0), "=r"(r1), "=r"(r2), "=r"(r3) : "r"(addr))

#define LDSM_X4_T(r0, r1, r2, r3, addr) \
    asm volatile("ldmatrix.sync.aligned.m8n8.x4.trans.shared.b16 {%0,%1,%2,%3}, [%4];" \
        : "=r"(r0), "=r"(r1), "=r"(r2), "=r"(r3) : "r"(addr))

#define MMA_BF16(c, a, b0v, b1v) \
    asm volatile("mma.sync.aligned.m16n8k16.row.col.f32.bf16.bf16.f32 " \
        "{%0,%1,%2,%3}, {%4,%5,%6,%7}, {%8,%9}, {%0,%1,%2,%3};" \
        : "+f"((c)[0]), "+f"((c)[1]), "+f"((c)[2]), "+f"((c)[3]) \
        : "r"((a)[0]), "r"((a)[1]), "r"((a)[2]), "r"((a)[3]), \
          "r"(b0v), "r"(b1v))

// split a float pair into bf16 hi/lo packed regs
__device__ __forceinline__ void split_pack2(float x, float y,
                                            uint32_t& hi, uint32_t& lo)
{
    __nv_bfloat16 hx = __float2bfloat16(x);
    __nv_bfloat16 hy = __float2bfloat16(y);
    __nv_bfloat16 lx = __float2bfloat16(x - __bfloat162float(hx));
    __nv_bfloat16 ly = __float2bfloat16(y - __bfloat162float(hy));
    uint16_t hxb = *(uint16_t*)&hx, hyb = *(uint16_t*)&hy;
    uint16_t lxb = *(uint16_t*)&lx, lyb = *(uint16_t*)&ly;
    hi = ((uint32_t)hyb << 16) | hxb;
    lo = ((uint32_t)lyb << 16) | lxb;
}

__device__ __forceinline__ void store_split2(float x, float y,
                                             __nv_bfloat16* Ph,
                                             __nv_bfloat16* Pl, long idx)
{
    __nv_bfloat16 hx = __float2bfloat16(x);
    __nv_bfloat16 hy = __float2bfloat16(y);
    __nv_bfloat16 lx = __float2bfloat16(x - __bfloat162float(hx));
    __nv_bfloat16 ly = __float2bfloat16(y - __bfloat162float(hy));
    *(__nv_bfloat162*)(Ph + idx) = __nv_bfloat162(hx, hy);
    *(__nv_bfloat162*)(Pl + idx) = __nv_bfloat162(lx, ly);
}

// ---------------------------------------------------------------------------
// Conversion kernels
// ---------------------------------------------------------------------------
__global__ void split_bf16_kernel(const float* __restrict__ x,
                                  __nv_bfloat16* __restrict__ hi,
                                  __nv_bfloat16* __restrict__ lo, int n4)
{
    int i = blockIdx.x * blockDim.x + threadIdx.x;
    if (i >= n4) return;
    float4 v = ((const float4*)x)[i];
    __nv_bfloat16 h0 = __float2bfloat16(v.x);
    __nv_bfloat16 h1 = __float2bfloat16(v.y);
    __nv_bfloat16 h2 = __float2bfloat16(v.z);
    __nv_bfloat16 h3 = __float2bfloat16(v.w);
    __nv_bfloat16 l0 = __float2bfloat16(v.x - __bfloat162float(h0));
    __nv_bfloat16 l1 = __float2bfloat16(v.y - __bfloat162float(h1));
    __nv_bfloat16 l2 = __float2bfloat16(v.z - __bfloat162float(h2));
    __nv_bfloat16 l3 = __float2bfloat16(v.w - __bfloat162float(h3));
    __nv_bfloat162* hp = (__nv_bfloat162*)hi;
    __nv_bfloat162* lp = (__nv_bfloat162*)lo;
    hp[2 * i]     = __nv_bfloat162(h0, h1);
    hp[2 * i + 1] = __nv_bfloat162(h2, h3);
    lp[2 * i]     = __nv_bfloat162(l0, l1);
    lp[2 * i + 1] = __nv_bfloat162(l2, l3);
}

__global__ void transpose_split_kernel(const float* __restrict__ W,
                                       __nv_bfloat16* __restrict__ hiT,
                                       __nv_bfloat16* __restrict__ loT,
                                       int K, int N)
{
    __shared__ float t[32][33];
    const int nB = blockIdx.x * 32;
    const int kB = blockIdx.y * 32;
    const int tx = threadIdx.x, ty = threadIdx.y;
#pragma unroll
    for (int i = 0; i < 4; i++)
        t[ty + 8 * i][tx] = W[(long)(kB + ty + 8 * i) * N + nB + tx];
    __syncthreads();
#pragma unroll
    for (int i = 0; i < 4; i++) {
        float v = t[tx][ty + 8 * i];
        __nv_bfloat16 h = __float2bfloat16(v);
        long o = (long)(nB + ty + 8 * i) * K + kB + tx;
        hiT[o] = h;
        loT[o] = __float2bfloat16(v - __bfloat162float(h));
    }
}

// ---------------------------------------------------------------------------
// Shared GEMM mainloop (bf16-split, mma.sync). Fills acc[4][4][4] fp32.
// ---------------------------------------------------------------------------
#define G_TILE_B 16384
#define G_BUF_B  (4 * G_TILE_B)
#define G_SMEM_REQ (2 * G_BUF_B)

__device__ __forceinline__ void gemm_core(
    const __nv_bfloat16* __restrict__ Ahi,
    const __nv_bfloat16* __restrict__ Alo,
    const __nv_bfloat16* __restrict__ Bhi,
    const __nv_bfloat16* __restrict__ Blo,
    int K, int rowBase, int colBase, float (&acc)[4][4][4])
{
    extern __shared__ char smem[];
    const uint32_t sbase = smem_to_u32(smem);
    const int tid  = threadIdx.x;
    const int wid  = tid >> 5;
    const int lane = tid & 31;
    const int wm   = wid & 1;
    const int wn   = wid >> 1;
    const int NCH  = K >> 6;

    const int ldr = tid >> 3;
    const int ldc = tid & 7;

    auto load_chunk = [&](int ch) {
        const uint32_t bb = sbase + (uint32_t)(ch & 1) * G_BUF_B;
        const long k0 = (long)ch * 64 + ldc * 8;
#pragma unroll
        for (int i = 0; i < 4; i++) {
            const int r = ldr + i * 32;
            const uint32_t sw = SWZ128((uint32_t)(r * 128 + ldc * 16));
            const long ao = (long)(rowBase + r) * K + k0;
            const long bo = (long)(colBase + r) * K + k0;
            CP_ASYNC16(bb + sw,                 Ahi + ao);
            CP_ASYNC16(bb + G_TILE_B + sw,      Alo + ao);
            CP_ASYNC16(bb + 2 * G_TILE_B + sw,  Bhi + bo);
            CP_ASYNC16(bb + 3 * G_TILE_B + sw,  Blo + bo);
        }
    };

    const int a_row  = lane & 15;
    const int a_colb = (lane >> 4) << 4;
    const int b_row  = (lane & 7) + ((lane & 16) ? 8 : 0);
    const int b_colb = (lane & 8) ? 16 : 0;

    load_chunk(0);
    CP_COMMIT();

    for (int ch = 0; ch < NCH; ch++) {
        __syncthreads();
        if (ch + 1 < NCH) load_chunk(ch + 1);
        CP_COMMIT();
        CP_WAIT1();
        __syncthreads();

        const uint32_t bb  = sbase + (uint32_t)(ch & 1) * G_BUF_B;
        const uint32_t aHi = bb;
        const uint32_t aLo = bb + G_TILE_B;
        const uint32_t bHi = bb + 2 * G_TILE_B;
        const uint32_t bLo = bb + 3 * G_TILE_B;

#pragma unroll
        for (int ks = 0; ks < 4; ks++) {
            const int kb = ks * 32;
            uint32_t ahi[4][4], alo[4][4];
#pragma unroll
            for (int mi = 0; mi < 4; mi++) {
                const int r = wm * 64 + mi * 16 + a_row;
                const uint32_t off = SWZ128((uint32_t)(r * 128 + kb + a_colb));
                LDSM_X4(ahi[mi][0], ahi[mi][1], ahi[mi][2], ahi[mi][3], aHi + off);
                LDSM_X4(alo[mi][0], alo[mi][1], alo[mi][2], alo[mi][3], aLo + off);
            }
            uint32_t bhi[4][2], blo[4][2];
#pragma unroll
            for (int njp = 0; njp < 2; njp++) {
                const int n = wn * 32 + njp * 16 + b_row;
                const uint32_t off = SWZ128((uint32_t)(n * 128 + kb + b_colb));
                uint32_t r0, r1, r2, r3;
                LDSM_X4(r0, r1, r2, r3, bHi + off);
                bhi[njp * 2][0] = r0;     bhi[njp * 2][1] = r1;
                bhi[njp * 2 + 1][0] = r2; bhi[njp * 2 + 1][1] = r3;
                LDSM_X4(r0, r1, r2, r3, bLo + off);
                blo[njp * 2][0] = r0;     blo[njp * 2][1] = r1;
                blo[njp * 2 + 1][0] = r2; blo[njp * 2 + 1][1] = r3;
            }
#pragma unroll
            for (int mi = 0; mi < 4; mi++)
#pragma unroll
                for (int nj = 0; nj < 4; nj++) {
                    MMA_BF16(acc[mi][nj], ahi[mi], bhi[nj][0], bhi[nj][1]);
                    MMA_BF16(acc[mi][nj], ahi[mi], blo[nj][0], blo[nj][1]);
                    MMA_BF16(acc[mi][nj], alo[mi], bhi[nj][0], bhi[nj][1]);
                }
        }
    }
}

// --- proj GEMM: fp32 C + bias --------------------------------------------
__global__ __launch_bounds__(256, 1)
void gemm_bias_out(const __nv_bfloat16* __restrict__ Ahi,
                   const __nv_bfloat16* __restrict__ Alo,
                   const __nv_bfloat16* __restrict__ Bhi,
                   const __nv_bfloat16* __restrict__ Blo,
                   const float* __restrict__ bias,
                   float* __restrict__ C, int N, int K)
{
    float acc[4][4][4];
#pragma unroll
    for (int i = 0; i < 4; i++)
#pragma unroll
        for (int j = 0; j < 4; j++)
#pragma unroll
            for (int v = 0; v < 4; v++) acc[i][j][v] = 0.0f;

    const int rowBase = blockIdx.y * 128;
    const int colBase = blockIdx.x * 128;
    gemm_core(Ahi, Alo, Bhi, Blo, K, rowBase, colBase, acc);

    const int lane = threadIdx.x & 31;
    const int wid  = threadIdx.x >> 5;
    const int wm = wid & 1, wn = wid >> 1;
#pragma unroll
    for (int mi = 0; mi < 4; mi++) {
        const int row = rowBase + wm * 64 + mi * 16 + (lane >> 2);
#pragma unroll
        for (int nj = 0; nj < 4; nj++) {
            const int col = colBase + wn * 32 + nj * 8 + (lane & 3) * 2;
            const float bx = bias[col], by = bias[col + 1];
            float2 v0, v1;
            v0.x = acc[mi][nj][0] + bx; v0.y = acc[mi][nj][1] + by;
            v1.x = acc[mi][nj][2] + bx; v1.y = acc[mi][nj][3] + by;
            *(float2*)(C + (long)row * N + col)       = v0;
            *(float2*)(C + (long)(row + 8) * N + col) = v1;
        }
    }
}

// --- QKV GEMM: epilogue splits into q/k/v bf16 hi/lo, [b,h,s,d] -----------
__global__ __launch_bounds__(256, 1)
void gemm_qkv(const __nv_bfloat16* __restrict__ Ahi,
              const __nv_bfloat16* __restrict__ Alo,
              const __nv_bfloat16* __restrict__ Bhi,
              const __nv_bfloat16* __restrict__ Blo,
              const float* __restrict__ bias,
              __nv_bfloat16* __restrict__ qhi, __nv_bfloat16* __restrict__ qlo,
              __nv_bfloat16* __restrict__ khi, __nv_bfloat16* __restrict__ klo,
              __nv_bfloat16* __restrict__ vhi, __nv_bfloat16* __restrict__ vlo)
{
    float acc[4][4][4];
#pragma unroll
    for (int i = 0; i < 4; i++)
#pragma unroll
        for (int j = 0; j < 4; j++)
#pragma unroll
            for (int v = 0; v < 4; v++) acc[i][j][v] = 0.0f;

    const int rowBase = blockIdx.y * 128;
    const int colBase = blockIdx.x * 128;
    gemm_core(Ahi, Alo, Bhi, Blo, NX_, rowBase, colBase, acc);

    const int lane = threadIdx.x & 31;
    const int wid  = threadIdx.x >> 5;
    const int wm = wid & 1, wn = wid >> 1;

    const int sec = colBase >> 10;              // 0=Q, 1=K, 2=V (uniform per CTA)
    __nv_bfloat16* dh = (sec == 0) ? qhi : (sec == 1) ? khi : vhi;
    __nv_bfloat16* dl = (sec == 0) ? qlo : (sec == 1) ? klo : vlo;
    const float scale = (sec == 0) ? 0.125f : 1.0f;

#pragma unroll
    for (int mi = 0; mi < 4; mi++) {
        const int row = rowBase + wm * 64 + mi * 16 + (lane >> 2);
#pragma unroll
        for (int nj = 0; nj < 4; nj++) {
            const int col = colBase + wn * 32 + nj * 8 + (lane & 3) * 2;
            const int cw = col & 1023;
            const int hh = cw >> 6;
            const int dd = cw & 63;
            const float bx = bias[col], by = bias[col + 1];
#pragma unroll
            for (int half = 0; half < 2; half++) {
                const int r = row + half * 8;
                const int bb = r >> 11;
                const int ss = r & 2047;
                const long idx = (((long)bb * NH_ + hh) * S_ + ss) * HD_ + dd;
                float x = (acc[mi][nj][half * 2]     + bx) * scale;
                float y = (acc[mi][nj][half * 2 + 1] + by) * scale;
                store_split2(x, y, dh, dl, idx);
            }
        }
    }
}

// ---------------------------------------------------------------------------
// Flash attention, tensor cores, bf16-split. 4 warps, BQ=BKT=64.
// Writes O pre-split hi/lo into proj input buffers [tok, h*64+d].
// ---------------------------------------------------------------------------
#define FA_SMEM 49152   // 6 tiles x 8192B (Qhi,Qlo,Khi,Klo,Vhi,Vlo)

__global__ __launch_bounds__(128)
void flash_attn_tc(const __nv_bfloat16* __restrict__ Qhi,
                   const __nv_bfloat16* __restrict__ Qlo,
                   const __nv_bfloat16* __restrict__ Khi,
                   const __nv_bfloat16* __restrict__ Klo,
                   const __nv_bfloat16* __restrict__ Vhi,
                   const __nv_bfloat16* __restrict__ Vlo,
                   __nv_bfloat16* __restrict__ Ohi,
                   __nv_bfloat16* __restrict__ Olo)
{
    extern __shared__ char smem[];
    const uint32_t sb = smem_to_u32(smem);
    const int tid  = threadIdx.x;
    const int wid  = tid >> 5;
    const int lane = tid & 31;
    const int qt = blockIdx.x, h = blockIdx.y, b = blockIdx.z;
    const long bh = (long)b * NH_ + h;
    const int q0 = qt * 64;

    // Q tile load (once)
#pragma unroll
    for (int t = 0; t < 4; t++) {
        const int v = tid + t * 128;
        const int r = v >> 3;
        const int cb = (v & 7) * 16;
        const uint32_t sw = SWZ128((uint32_t)(r * 128 + cb));
        const long g = (bh * S_ + q0 + r) * HD_ + (v & 7) * 8;
        *(uint4*)(smem + sw)        = *(const uint4*)(Qhi + g);
        *(uint4*)(smem + 8192 + sw) = *(const uint4*)(Qlo + g);
    }

    float m0 = -1e30f, m1 = -1e30f, l0 = 0.0f, l1 = 0.0f;
    float oacc[8][4];
#pragma unroll
    for (int i = 0; i < 8; i++)
#pragma unroll
        for (int j = 0; j < 4; j++) oacc[i][j] = 0.0f;

    const int a_row  = lane & 15;
    const int a_colb = (lane >> 4) << 4;
    const int b_row  = (lane & 7) + ((lane & 16) ? 8 : 0);
    const int b_colb = (lane & 8) ? 16 : 0;
    const int v_tok  = (lane & 7) + ((lane & 8) ? 8 : 0);
    const int v_colb = (lane & 16) ? 16 : 0;

    for (int kt = 0; kt <= qt; kt++) {
        __syncthreads();                     // prev K/V consumers done (+Q stores on it 0)
        const int k0 = kt * 64;
#pragma unroll
        for (int t = 0; t < 4; t++) {
            const int v = tid + t * 128;
            const int r = v >> 3;
            const int cb = (v & 7) * 16;
            const uint32_t sw = SWZ128((uint32_t)(r * 128 + cb));
            const long g = (bh * S_ + k0 + r) * HD_ + (v & 7) * 8;
            CP_ASYNC16(sb + 16384 + sw, Khi + g);
            CP_ASYNC16(sb + 24576 + sw, Klo + g);
            CP_ASYNC16(sb + 32768 + sw, Vhi + g);
            CP_ASYNC16(sb + 40960 + sw, Vlo + g);
        }
        CP_COMMIT();
        CP_WAIT0();
        __syncthreads();

        // --- S = Q @ K^T (3-term split) ---
        float sacc[8][4];
#pragma unroll
        for (int i = 0; i < 8; i++)
#pragma unroll
            for (int j = 0; j < 4; j++) sacc[i][j] = 0.0f;

#pragma unroll
        for (int kc = 0; kc < 4; kc++) {
            const int kb = kc * 32;
            uint32_t aqh[4], aql[4];
            const uint32_t qoff = SWZ128((uint32_t)((wid * 16 + a_row) * 128 + kb + a_colb));
            LDSM_X4(aqh[0], aqh[1], aqh[2], aqh[3], sb + qoff);
            LDSM_X4(aql[0], aql[1], aql[2], aql[3], sb + 8192 + qoff);
#pragma unroll
            for (int njp = 0; njp < 4; njp++) {
                const uint32_t koff = SWZ128((uint32_t)((njp * 16 + b_row) * 128 + kb + b_colb));
                uint32_t kh0, kh1, kh2, kh3, kl0, kl1, kl2, kl3;
                LDSM_X4(kh0, kh1, kh2, kh3, sb + 16384 + koff);
                LDSM_X4(kl0, kl1, kl2, kl3, sb + 24576 + koff);
                MMA_BF16(sacc[2 * njp],     aqh, kh0, kh1);
                MMA_BF16(sacc[2 * njp],     aqh, kl0, kl1);
                MMA_BF16(sacc[2 * njp],     aql, kh0, kh1);
                MMA_BF16(sacc[2 * njp + 1], aqh, kh2, kh3);
                MMA_BF16(sacc[2 * njp + 1], aqh, kl2, kl3);
                MMA_BF16(sacc[2 * njp + 1], aql, kh2, kh3);
            }
        }

        // --- causal mask on diagonal tile ---
        if (kt == qt) {
            const int rg = wid * 16 + (lane >> 2);
            const int c2 = (lane & 3) * 2;
#pragma unroll
            for (int nj = 0; nj < 8; nj++) {
                const int c = nj * 8 + c2;
                if (c     > rg)     sacc[nj][0] = -1e30f;
                if (c + 1 > rg)     sacc[nj][1] = -1e30f;
                if (c     > rg + 8) sacc[nj][2] = -1e30f;
                if (c + 1 > rg + 8) sacc[nj][3] = -1e30f;
            }
        }

        // --- online softmax (rows g, g+8 per lane-group of 4) ---
        float mx0 = -1e30f, mx1 = -1e30f;
#pragma unroll
        for (int nj = 0; nj < 8; nj++) {
            mx0 = fmaxf(mx0, fmaxf(sacc[nj][0], sacc[nj][1]));
            mx1 = fmaxf(mx1, fmaxf(sacc[nj][2], sacc[nj][3]));
        }
        mx0 = fmaxf(mx0, __shfl_xor_sync(0xffffffffu, mx0, 1));
        mx0 = fmaxf(mx0, __shfl_xor_sync(0xffffffffu, mx0, 2));
        mx1 = fmaxf(mx1, __shfl_xor_sync(0xffffffffu, mx1, 1));
        mx1 = fmaxf(mx1, __shfl_xor_sync(0xffffffffu, mx1, 2));
        const float mn0 = fmaxf(m0, mx0);
        const float mn1 = fmaxf(m1, mx1);
        const float sc0 = __expf(m0 - mn0);
        const float sc1 = __expf(m1 - mn1);
        float s0 = 0.0f, s1 = 0.0f;
#pragma unroll
        for (int nj = 0; nj < 8; nj++) {
            sacc[nj][0] = __expf(sacc[nj][0] - mn0); s0 += sacc[nj][0];
            sacc[nj][1] = __expf(sacc[nj][1] - mn0); s0 += sacc[nj][1];
            sacc[nj][2] = __expf(sacc[nj][2] - mn1); s1 += sacc[nj][2];
            sacc[nj][3] = __expf(sacc[nj][3] - mn1); s1 += sacc[nj][3];
        }
        s0 += __shfl_xor_sync(0xffffffffu, s0, 1);
        s0 += __shfl_xor_sync(0xffffffffu, s0, 2);
        s1 += __shfl_xor_sync(0xffffffffu, s1, 1);
        s1 += __shfl_xor_sync(0xffffffffu, s1, 2);
        l0 = l0 * sc0 + s0;
        l1 = l1 * sc1 + s1;
        m0 = mn0; m1 = mn1;
#pragma unroll
        for (int dt = 0; dt < 8; dt++) {
            oacc[dt][0] *= sc0; oacc[dt][1] *= sc0;
            oacc[dt][2] *= sc1; oacc[dt][3] *= sc1;
        }

        // --- pack P into A-fragments (hi/lo) ---
        uint32_t phi[4][4], plo[4][4];
#pragma unroll
        for (int kc = 0; kc < 4; kc++) {
            split_pack2(sacc[2 * kc][0],     sacc[2 * kc][1],     phi[kc][0], plo[kc][0]);
            split_pack2(sacc[2 * kc][2],     sacc[2 * kc][3],     phi[kc][1], plo[kc][1]);
            split_pack2(sacc[2 * kc + 1][0], sacc[2 * kc + 1][1], phi[kc][2], plo[kc][2]);
            split_pack2(sacc[2 * kc + 1][2], sacc[2 * kc + 1][3], phi[kc][3], plo[kc][3]);
        }

        // --- O += P @ V (3-term split, V via ldmatrix.trans) ---
#pragma unroll
        for (int kc = 0; kc < 4; kc++) {
#pragma unroll
            for (int djp = 0; djp < 4; djp++) {
                const uint32_t voff =
                    SWZ128((uint32_t)((kc * 16 + v_tok) * 128 + djp * 32 + v_colb));
                uint32_t vh0, vh1, vh2, vh3, vl0, vl1, vl2, vl3;
                LDSM_X4_T(vh0, vh1, vh2, vh3, sb + 32768 + voff);
                LDSM_X4_T(vl0, vl1, vl2, vl3, sb + 40960 + voff);
                MMA_BF16(oacc[2 * djp],     phi[kc], vh0, vh1);
                MMA_BF16(oacc[2 * djp],     phi[kc], vl0, vl1);
                MMA_BF16(oacc[2 * djp],     plo[kc], vh0, vh1);
                MMA_BF16(oacc[2 * djp + 1], phi[kc], vh2, vh3);
                MMA_BF16(oacc[2 * djp + 1], phi[kc], vl2, vl3);
                MMA_BF16(oacc[2 * djp + 1], plo[kc], vh2, vh3);
            }
        }
    }

    // --- finalize: O/l, split hi/lo, write [tok, h*64+d] ---
    const float i0 = 1.0f / l0;
    const float i1 = 1.0f / l1;
    const int rg = q0 + wid * 16 + (lane >> 2);
    const long tok0 = (long)b * S_ + rg;
    const long tok1 = tok0 + 8;
#pragma unroll
    for (int dt = 0; dt < 8; dt++) {
        const int col = h * HD_ + dt * 8 + (lane & 3) * 2;
        store_split2(oacc[dt][0] * i0, oacc[dt][1] * i0, Ohi, Olo, tok0 * NX_ + col);
        store_split2(oacc[dt][2] * i1, oacc[dt][3] * i1, Ohi, Olo, tok1 * NX_ + col);
    }
}

// ---------------------------------------------------------------------------
// Launch
// ---------------------------------------------------------------------------
extern "C" void kernel_launch(void* const* d_in, const int* in_sizes, int n_in,
                              void* d_out, int out_size)
{
    (void)in_sizes; (void)n_in; (void)out_size;
    const float* hidden   = (const float*)d_in[0];
    const float* c_attn_w = (const float*)d_in[1];
    const float* c_attn_b = (const float*)d_in[2];
    const float* c_proj_w = (const float*)d_in[3];
    const float* c_proj_b = (const float*)d_in[4];
    float* out = (float*)d_out;

    void *xhi_p, *xlo_p, *wqh_p, *wql_p, *wph_p, *wpl_p;
    void *qh_p, *ql_p, *kh_p, *kl_p, *vh_p, *vl_p;
    cudaGetSymbolAddress(&xhi_p, g_xhi);
    cudaGetSymbolAddress(&xlo_p, g_xlo);
    cudaGetSymbolAddress(&wqh_p, g_wqT_hi);
    cudaGetSymbolAddress(&wql_p, g_wqT_lo);
    cudaGetSymbolAddress(&wph_p, g_wpT_hi);
    cudaGetSymbolAddress(&wpl_p, g_wpT_lo);
    cudaGetSymbolAddress(&qh_p, g_qhi);
    cudaGetSymbolAddress(&ql_p, g_qlo);
    cudaGetSymbolAddress(&kh_p, g_khi);
    cudaGetSymbolAddress(&kl_p, g_klo);
    cudaGetSymbolAddress(&vh_p, g_vhi);
    cudaGetSymbolAddress(&vl_p, g_vlo);
    __nv_bfloat16* xhi = (__nv_bfloat16*)xhi_p;
    __nv_bfloat16* xlo = (__nv_bfloat16*)xlo_p;
    __nv_bfloat16* wqh = (__nv_bfloat16*)wqh_p;
    __nv_bfloat16* wql = (__nv_bfloat16*)wql_p;
    __nv_bfloat16* wph = (__nv_bfloat16*)wph_p;
    __nv_bfloat16* wpl = (__nv_bfloat16*)wpl_p;
    __nv_bfloat16* qhi = (__nv_bfloat16*)qh_p;
    __nv_bfloat16* qlo = (__nv_bfloat16*)ql_p;
    __nv_bfloat16* khi = (__nv_bfloat16*)kh_p;
    __nv_bfloat16* klo = (__nv_bfloat16*)kl_p;
    __nv_bfloat16* vhi = (__nv_bfloat16*)vh_p;
    __nv_bfloat16* vlo = (__nv_bfloat16*)vl_p;

    static bool attr_done = false;
    if (!attr_done) {
        cudaFuncSetAttribute(gemm_qkv,
                             cudaFuncAttributeMaxDynamicSharedMemorySize, G_SMEM_REQ);
        cudaFuncSetAttribute(gemm_bias_out,
                             cudaFuncAttributeMaxDynamicSharedMemorySize, G_SMEM_REQ);
        cudaFuncSetAttribute(flash_attn_tc,
                             cudaFuncAttributeMaxDynamicSharedMemorySize, FA_SMEM);
        attr_done = true;
    }

    // 1) split hidden -> xhi/xlo
    {
        int n4 = MROWS * NX_ / 4;
        split_bf16_kernel<<<(n4 + 255) / 256, 256>>>(hidden, xhi, xlo, n4);
    }
    // 2) transpose+split weights
    {
        dim3 g1(N3X_ / 32, NX_ / 32);
        transpose_split_kernel<<<g1, dim3(32, 8)>>>(c_attn_w, wqh, wql, NX_, N3X_);
        dim3 g2(NX_ / 32, NX_ / 32);
        transpose_split_kernel<<<g2, dim3(32, 8)>>>(c_proj_w, wph, wpl, NX_, NX_);
    }
    // 3) QKV projection -> split q/k/v [b,h,s,d]
    {
        dim3 grid(N3X_ / 128, MROWS / 128);
        gemm_qkv<<<grid, 256, G_SMEM_REQ>>>(xhi, xlo, wqh, wql, c_attn_b,
                                            qhi, qlo, khi, klo, vhi, vlo);
    }
    // 4) flash attention (tensor cores) -> xhi/xlo
    {
        dim3 grid(S_ / 64, NH_, B_);
        flash_attn_tc<<<grid, 128, FA_SMEM>>>(qhi, qlo, khi, klo, vhi, vlo,
                                              xhi, xlo);
    }
    // 5) output projection -> d_out
    {
        dim3 grid(NX_ / 128, MROWS / 128);
        gemm_bias_out<<<grid, 256, G_SMEM_REQ>>>(xhi, xlo, wph, wpl,
                                                 c_proj_b, out, NX_, NX_);
    }
}